// round 14
// baseline (speedup 1.0000x reference)
#include <cuda_runtime.h>
#include <cuda_bf16.h>
#include <cuda_fp16.h>
#include <stdint.h>

#define BATCH 4
#define SEQ_Q 4096
#define SEQ_V 4096
#define HDIM  64

#define TQ 64                   // q rows per CTA
#define TN 128                  // kv rows per tile
#define KVSPLIT 8
#define KVCHUNK (SEQ_V / KVSPLIT)       // 512
#define TILES_PER_CTA (KVCHUNK / TN)    // 4
#define NT 128                  // 4 warps

#define SWZ(x) ((uint32_t)(x) ^ ((((uint32_t)(x)) >> 3) & 0x70u))

// smem: QH16[8K] | QL16[8K] | 2 x Vbuf{ V16[16K] | VBH[16K] | VBL[16K] }
#define SM_QH 0
#define SM_QL 8192
#define SM_V  16384
#define VBUF_SZ 49152
#define OFF_V16 0
#define OFF_VBH 16384
#define OFF_VBL 32768
#define SMEM_TOTAL (SM_V + 2 * VBUF_SZ)   // 114688

// prepacked operands (pairs)
__device__ uint32_t g_qh[(size_t)BATCH * SEQ_Q * HDIM / 2];   // fp16 hi of Q*log2e
__device__ uint32_t g_ql[(size_t)BATCH * SEQ_Q * HDIM / 2];   // fp16 lo
__device__ uint32_t g_v16[(size_t)BATCH * SEQ_V * HDIM / 2];  // fp16 V (for S)
__device__ uint32_t g_vh[(size_t)BATCH * SEQ_V * HDIM / 2];   // bf16 hi V (for PV)
__device__ uint32_t g_vl[(size_t)BATCH * SEQ_V * HDIM / 2];   // bf16 lo V
// cross-CTA accumulators
__device__ float g_oacc[(size_t)BATCH * SEQ_Q * HDIM];
__device__ float g_lacc[(size_t)BATCH * SEQ_Q];

static __device__ __forceinline__ uint32_t smem_u32(const void* p) {
    uint32_t a;
    asm("{ .reg .u64 t; cvta.to.shared.u64 t, %1; cvt.u32.u64 %0, t; }" : "=r"(a) : "l"(p));
    return a;
}

// pack (x,y) -> bf16x2 hi word-pair + residual lo pair
static __device__ __forceinline__ void split_pack_bf(float x, float y,
                                                     uint32_t& hi, uint32_t& lo) {
    asm("cvt.rn.bf16x2.f32 %0, %1, %2;" : "=r"(hi) : "f"(y), "f"(x));
    float xh = __uint_as_float(hi << 16);
    float yh = __uint_as_float(hi & 0xFFFF0000u);
    asm("cvt.rn.bf16x2.f32 %0, %1, %2;" : "=r"(lo) : "f"(y - yh), "f"(x - xh));
}

// pack (x,y) -> fp16x2 hi word-pair + residual lo pair
static __device__ __forceinline__ void split_pack_f16(float x, float y,
                                                      uint32_t& hi, uint32_t& lo) {
    __half2 h = __floats2half2_rn(x, y);
    hi = *(uint32_t*)&h;
    float2 f = __half22float2(h);
    __half2 l = __floats2half2_rn(x - f.x, y - f.y);
    lo = *(uint32_t*)&l;
}

// pack (x,y) -> bf16x2 (round-to-nearest)
static __device__ __forceinline__ uint32_t pack_bf2(float x, float y) {
    uint32_t r;
    asm("cvt.rn.bf16x2.f32 %0, %1, %2;" : "=r"(r) : "f"(y), "f"(x));
    return r;
}

#define CP16(dst, src) \
    asm volatile("cp.async.cg.shared.global [%0], [%1], 16;" :: "r"(dst), "l"(src) : "memory")
#define CP_COMMIT() asm volatile("cp.async.commit_group;" ::: "memory")
#define CP_WAIT0()  asm volatile("cp.async.wait_group 0;" ::: "memory")
#define CP_WAIT1()  asm volatile("cp.async.wait_group 1;" ::: "memory")

#define LDSM4(R, addr) \
    asm volatile("ldmatrix.sync.aligned.m8n8.x4.shared.b16 {%0,%1,%2,%3}, [%4];" \
        : "=r"((R)[0]), "=r"((R)[1]), "=r"((R)[2]), "=r"((R)[3]) : "r"(addr))
#define LDSM4T(R, addr) \
    asm volatile("ldmatrix.sync.aligned.m8n8.x4.trans.shared.b16 {%0,%1,%2,%3}, [%4];" \
        : "=r"((R)[0]), "=r"((R)[1]), "=r"((R)[2]), "=r"((R)[3]) : "r"(addr))

#define MMA_BF16(C, A, b0_, b1_) \
    asm volatile("mma.sync.aligned.m16n8k16.row.col.f32.bf16.bf16.f32 " \
        "{%0,%1,%2,%3}, {%4,%5,%6,%7}, {%8,%9}, {%0,%1,%2,%3};" \
        : "+f"((C)[0]), "+f"((C)[1]), "+f"((C)[2]), "+f"((C)[3]) \
        : "r"((A)[0]), "r"((A)[1]), "r"((A)[2]), "r"((A)[3]), "r"(b0_), "r"(b1_))

#define MMA_F16(C, A, b0_, b1_) \
    asm volatile("mma.sync.aligned.m16n8k16.row.col.f32.f16.f16.f32 " \
        "{%0,%1,%2,%3}, {%4,%5,%6,%7}, {%8,%9}, {%0,%1,%2,%3};" \
        : "+f"((C)[0]), "+f"((C)[1]), "+f"((C)[2]), "+f"((C)[3]) \
        : "r"((A)[0]), "r"((A)[1]), "r"((A)[2]), "r"((A)[3]), "r"(b0_), "r"(b1_))

#define REDV2(ptr, a, b) \
    asm volatile("red.global.add.v2.f32 [%0], {%1, %2};" :: "l"(ptr), "f"(a), "f"(b) : "memory")

static __device__ __forceinline__ float ex2f(float x) {
    float r; asm("ex2.approx.f32 %0, %1;" : "=f"(r) : "f"(x)); return r;
}
static __device__ __forceinline__ float bf_lo(uint32_t p) {
    return __uint_as_float(p << 16);
}
static __device__ __forceinline__ float bf_hi(uint32_t p) {
    return __uint_as_float(p & 0xFFFF0000u);
}

// ---------------- pre-pass (split-role): Q blocks and V blocks ----------------
__global__ void convert_kernel(const float* __restrict__ Q, const float* __restrict__ V) {
    int bid = blockIdx.x;
    int i = (bid & 1023) * blockDim.x + threadIdx.x;   // float4 index, 0..262143
    const float L2E = 1.4426950408889634f;

    if (bid < 1024) {
        // ---- Q path
        float4 q = ((const float4*)Q)[i];
        uint2 qh, ql;
        split_pack_f16(q.x * L2E, q.y * L2E, qh.x, ql.x);
        split_pack_f16(q.z * L2E, q.w * L2E, qh.y, ql.y);
        ((uint2*)g_qh)[i] = qh;
        ((uint2*)g_ql)[i] = ql;
        ((float4*)g_oacc)[i] = make_float4(0.f, 0.f, 0.f, 0.f);
    } else {
        // ---- V path
        float4 v = ((const float4*)V)[i];
        uint2 v16;
        {
            __half2 a = __floats2half2_rn(v.x, v.y);
            __half2 b = __floats2half2_rn(v.z, v.w);
            v16.x = *(uint32_t*)&a;
            v16.y = *(uint32_t*)&b;
        }
        ((uint2*)g_v16)[i] = v16;
        uint2 vh, vl;
        split_pack_bf(v.x, v.y, vh.x, vl.x);
        split_pack_bf(v.z, v.w, vh.y, vl.y);
        ((uint2*)g_vh)[i] = vh;
        ((uint2*)g_vl)[i] = vl;
        if (i < (BATCH * SEQ_Q) / 4) ((float4*)g_lacc)[i] = make_float4(0.f, 0.f, 0.f, 0.f);
    }
}

// ---------------- main attention kernel ----------------
static __device__ __forceinline__ void load_v_tile(uint32_t sb, int b, int kvrow,
                                                   int buf, int tid) {
    const size_t eoff = (size_t)(b * SEQ_V + kvrow) * HDIM * 2;
    const char* g16 = (const char*)g_v16 + eoff;
    const char* gh  = (const char*)g_vh  + eoff;
    const char* gl  = (const char*)g_vl  + eoff;
    uint32_t base = sb + SM_V + buf * VBUF_SZ;
#pragma unroll
    for (int i = 0; i < 8; i++) {
        uint32_t off = (uint32_t)(tid + i * NT) * 16;   // 1024 x 16B = 16KB each
        CP16(base + OFF_V16 + SWZ(off), g16 + off);
        CP16(base + OFF_VBH + SWZ(off), gh + off);
        CP16(base + OFF_VBL + SWZ(off), gl + off);
    }
}

__global__ __launch_bounds__(NT, 2)
void attn_mma_kernel()
{
    extern __shared__ char smem[];
    const uint32_t sb = smem_u32(smem);
    const int tid = threadIdx.x;
    const int l = tid & 31, w = tid >> 5;
    const int qt = blockIdx.x & 255;     // (b, q64)
    const int kc = blockIdx.x >> 8;      // kv chunk 0..7
    const int b = qt >> 6;
    const int qrow0 = (qt & 63) * TQ;    // within batch
    const int kv0 = kc * KVCHUNK;

    // ---- prologue: Q (fp16 hi+lo) + V tile 0
    {
        const char* gqh = (const char*)g_qh + (size_t)(b * SEQ_Q + qrow0) * HDIM * 2;
        const char* gql = (const char*)g_ql + (size_t)(b * SEQ_Q + qrow0) * HDIM * 2;
#pragma unroll
        for (int i = 0; i < 4; i++) {
            uint32_t off = (uint32_t)(tid + i * NT) * 16;   // 512 x 16B = 8KB
            CP16(sb + SM_QH + SWZ(off), gqh + off);
            CP16(sb + SM_QL + SWZ(off), gql + off);
        }
        load_v_tile(sb, b, kv0, 0, tid);
        CP_COMMIT();
        CP_WAIT0();
        __syncthreads();
    }

    // ---- Q A-fragments (per warp: rows w*16..w*16+15)
    uint32_t aqh[4][4], aql[4][4];
    {
        int qrow = w * 16 + (l & 15);
#pragma unroll
        for (int kk = 0; kk < 4; kk++) {
            uint32_t off = SWZ((uint32_t)qrow * 128 + kk * 32 + ((l >> 4) & 1) * 16);
            LDSM4(aqh[kk], sb + SM_QH + off);
            LDSM4(aql[kk], sb + SM_QL + off);
        }
    }

    float oc[8][4];
#pragma unroll
    for (int f = 0; f < 8; f++) { oc[f][0] = oc[f][1] = oc[f][2] = oc[f][3] = 0.f; }
    float lsum0 = 0.f, lsum1 = 0.f;

    for (int t = 0; t < TILES_PER_CTA; t++) {
        __syncthreads();
        if (t + 1 < TILES_PER_CTA) {
            load_v_tile(sb, b, kv0 + (t + 1) * TN, (t + 1) & 1, tid);
            CP_COMMIT();
            CP_WAIT1();
        } else {
            CP_WAIT0();
        }
        __syncthreads();

        const uint32_t vbase = sb + SM_V + (t & 1) * VBUF_SZ;
        const uint32_t v16b = vbase + OFF_V16;
        const uint32_t vbhb = vbase + OFF_VBH;
        const uint32_t vblb = vbase + OFF_VBL;

        // ---- S' = (Q*log2e) . V^T  (fp16x2: exact Q split, V fp16 once)
        float sc[16][4];
#pragma unroll
        for (int f = 0; f < 16; f++) { sc[f][0] = sc[f][1] = sc[f][2] = sc[f][3] = 0.f; }

#pragma unroll
        for (int kk = 0; kk < 4; kk++) {
#pragma unroll
            for (int np = 0; np < 8; np++) {
                uint32_t off = SWZ((uint32_t)(16 * np + (l & 7) + ((l >> 4) & 1) * 8) * 128
                                   + kk * 32 + ((l >> 3) & 1) * 16);
                uint32_t bh[4];
                LDSM4(bh, v16b + off);
                MMA_F16(sc[2 * np],     aqh[kk], bh[0], bh[1]);
                MMA_F16(sc[2 * np + 1], aqh[kk], bh[2], bh[3]);
                MMA_F16(sc[2 * np],     aql[kk], bh[0], bh[1]);
                MMA_F16(sc[2 * np + 1], aql[kk], bh[2], bh[3]);
            }
        }

        // ---- softmax: p = 2^(s')
#pragma unroll
        for (int f = 0; f < 16; f++) {
            sc[f][0] = ex2f(sc[f][0]);
            sc[f][1] = ex2f(sc[f][1]);
            sc[f][2] = ex2f(sc[f][2]);
            sc[f][3] = ex2f(sc[f][3]);
        }

        // ---- O += P . V  (P bf16 once; V bf16 hi/lo; denominator from the
        //      SAME rounded P so numerator/denominator weights are consistent)
#pragma unroll
        for (int kcc = 0; kcc < 8; kcc++) {
            uint32_t ah[4];
            ah[0] = pack_bf2(sc[2 * kcc][0],     sc[2 * kcc][1]);
            ah[1] = pack_bf2(sc[2 * kcc][2],     sc[2 * kcc][3]);
            ah[2] = pack_bf2(sc[2 * kcc + 1][0], sc[2 * kcc + 1][1]);
            ah[3] = pack_bf2(sc[2 * kcc + 1][2], sc[2 * kcc + 1][3]);
            lsum0 += (bf_lo(ah[0]) + bf_hi(ah[0])) + (bf_lo(ah[2]) + bf_hi(ah[2]));
            lsum1 += (bf_lo(ah[1]) + bf_hi(ah[1])) + (bf_lo(ah[3]) + bf_hi(ah[3]));
#pragma unroll
            for (int dp = 0; dp < 4; dp++) {
                uint32_t off = SWZ((uint32_t)(16 * kcc + (l & 7) + ((l >> 3) & 1) * 8) * 128
                                   + dp * 32 + ((l >> 4) & 1) * 16);
                uint32_t vh[4], vl[4];
                LDSM4T(vh, vbhb + off);
                LDSM4T(vl, vblb + off);
                MMA_BF16(oc[2 * dp],     ah, vh[0], vh[1]);
                MMA_BF16(oc[2 * dp + 1], ah, vh[2], vh[3]);
                MMA_BF16(oc[2 * dp],     ah, vl[0], vl[1]);
                MMA_BF16(oc[2 * dp + 1], ah, vl[2], vl[3]);
            }
        }
    }

    // ---- merge partials: row sums + unnormalized O (vector reductions)
    lsum0 += __shfl_xor_sync(0xFFFFFFFFu, lsum0, 1);
    lsum0 += __shfl_xor_sync(0xFFFFFFFFu, lsum0, 2);
    lsum1 += __shfl_xor_sync(0xFFFFFFFFu, lsum1, 1);
    lsum1 += __shfl_xor_sync(0xFFFFFFFFu, lsum1, 2);

    const int row0 = qrow0 + w * 16 + (l >> 2);
    float* oa = g_oacc + ((size_t)b * SEQ_Q + row0) * HDIM;
    float* ob = oa + 8 * HDIM;    // row0 + 8
    const int cb = 2 * (l & 3);
#pragma unroll
    for (int f = 0; f < 8; f++) {
        REDV2(oa + 8 * f + cb, oc[f][0], oc[f][1]);
        REDV2(ob + 8 * f + cb, oc[f][2], oc[f][3]);
    }
    if ((l & 3) == 0) {
        atomicAdd(g_lacc + (size_t)b * SEQ_Q + row0,     lsum0);
        atomicAdd(g_lacc + (size_t)b * SEQ_Q + row0 + 8, lsum1);
    }
}

// ---------------- normalize: O = acc / l ----------------
__global__ void normalize_kernel(float* __restrict__ O) {
    int i = blockIdx.x * blockDim.x + threadIdx.x;   // float4 units, 262144
    int row = i >> 4;                                // 16 float4 per row
    float inv = 1.0f / g_lacc[row];
    float4 v = ((const float4*)g_oacc)[i];
    ((float4*)O)[i] = make_float4(v.x * inv, v.y * inv, v.z * inv, v.w * inv);
}

extern "C" void kernel_launch(void* const* d_in, const int* in_sizes, int n_in,
                              void* d_out, int out_size)
{
    const float* Q = (const float*)d_in[0];
    const float* V = (const float*)d_in[1];
    float* O = (float*)d_out;

    convert_kernel<<<2048, 256>>>(Q, V);

    cudaFuncSetAttribute(attn_mma_kernel,
                         cudaFuncAttributeMaxDynamicSharedMemorySize, SMEM_TOTAL);
    attn_mma_kernel<<<256 * KVSPLIT, NT, SMEM_TOTAL>>>();

    normalize_kernel<<<(BATCH * SEQ_Q * HDIM / 4) / 256, 256>>>(O);
}

// round 15
// speedup vs baseline: 1.1884x; 1.1884x over previous
#include <cuda_runtime.h>
#include <cuda_bf16.h>
#include <cuda_fp16.h>
#include <stdint.h>

#define BATCH 4
#define SEQ_Q 4096
#define SEQ_V 4096
#define HDIM  64

#define TQ 64                   // q rows per CTA
#define TN 128                  // kv rows per tile
#define KVSPLIT 4
#define KVCHUNK (SEQ_V / KVSPLIT)       // 1024
#define TILES_PER_CTA (KVCHUNK / TN)    // 8
#define NT 128                  // 4 warps

#define SWZ(x) ((uint32_t)(x) ^ ((((uint32_t)(x)) >> 3) & 0x70u))

// smem: QH16[8K] | QL16[8K] | 2 x Vbuf{ V16[16K] }
#define SM_QH 0
#define SM_QL 8192
#define SM_V  16384
#define VBUF_SZ 16384
#define SMEM_TOTAL (SM_V + 2 * VBUF_SZ)   // 49152

// prepacked operands (pairs)
__device__ uint32_t g_qh[(size_t)BATCH * SEQ_Q * HDIM / 2];   // fp16 hi of Q*log2e
__device__ uint32_t g_ql[(size_t)BATCH * SEQ_Q * HDIM / 2];   // fp16 lo
__device__ uint32_t g_v16[(size_t)BATCH * SEQ_V * HDIM / 2];  // fp16 V (S and PV)
// cross-CTA accumulators
__device__ float g_oacc[(size_t)BATCH * SEQ_Q * HDIM];
__device__ float g_lacc[(size_t)BATCH * SEQ_Q];

static __device__ __forceinline__ uint32_t smem_u32(const void* p) {
    uint32_t a;
    asm("{ .reg .u64 t; cvta.to.shared.u64 t, %1; cvt.u32.u64 %0, t; }" : "=r"(a) : "l"(p));
    return a;
}

// pack (x,y) -> fp16x2 hi word-pair + residual lo pair
static __device__ __forceinline__ void split_pack_f16(float x, float y,
                                                      uint32_t& hi, uint32_t& lo) {
    __half2 h = __floats2half2_rn(x, y);
    hi = *(uint32_t*)&h;
    float2 f = __half22float2(h);
    __half2 l = __floats2half2_rn(x - f.x, y - f.y);
    lo = *(uint32_t*)&l;
}

#define CP16(dst, src) \
    asm volatile("cp.async.cg.shared.global [%0], [%1], 16;" :: "r"(dst), "l"(src) : "memory")
#define CP_COMMIT() asm volatile("cp.async.commit_group;" ::: "memory")
#define CP_WAIT0()  asm volatile("cp.async.wait_group 0;" ::: "memory")
#define CP_WAIT1()  asm volatile("cp.async.wait_group 1;" ::: "memory")

#define LDSM4(R, addr) \
    asm volatile("ldmatrix.sync.aligned.m8n8.x4.shared.b16 {%0,%1,%2,%3}, [%4];" \
        : "=r"((R)[0]), "=r"((R)[1]), "=r"((R)[2]), "=r"((R)[3]) : "r"(addr))
#define LDSM4T(R, addr) \
    asm volatile("ldmatrix.sync.aligned.m8n8.x4.trans.shared.b16 {%0,%1,%2,%3}, [%4];" \
        : "=r"((R)[0]), "=r"((R)[1]), "=r"((R)[2]), "=r"((R)[3]) : "r"(addr))

#define MMA_F16(C, A, b0_, b1_) \
    asm volatile("mma.sync.aligned.m16n8k16.row.col.f32.f16.f16.f32 " \
        "{%0,%1,%2,%3}, {%4,%5,%6,%7}, {%8,%9}, {%0,%1,%2,%3};" \
        : "+f"((C)[0]), "+f"((C)[1]), "+f"((C)[2]), "+f"((C)[3]) \
        : "r"((A)[0]), "r"((A)[1]), "r"((A)[2]), "r"((A)[3]), "r"(b0_), "r"(b1_))

#define REDV2(ptr, a, b) \
    asm volatile("red.global.add.v2.f32 [%0], {%1, %2};" :: "l"(ptr), "f"(a), "f"(b) : "memory")

static __device__ __forceinline__ float ex2f(float x) {
    float r; asm("ex2.approx.f32 %0, %1;" : "=f"(r) : "f"(x)); return r;
}

// ---------------- pre-pass (split-role): Q blocks and V blocks ----------------
__global__ void convert_kernel(const float* __restrict__ Q, const float* __restrict__ V) {
    int bid = blockIdx.x;
    int i = (bid & 1023) * blockDim.x + threadIdx.x;   // float4 index, 0..262143
    const float L2E = 1.4426950408889634f;

    if (bid < 1024) {
        // ---- Q path
        float4 q = ((const float4*)Q)[i];
        uint2 qh, ql;
        split_pack_f16(q.x * L2E, q.y * L2E, qh.x, ql.x);
        split_pack_f16(q.z * L2E, q.w * L2E, qh.y, ql.y);
        ((uint2*)g_qh)[i] = qh;
        ((uint2*)g_ql)[i] = ql;
        ((float4*)g_oacc)[i] = make_float4(0.f, 0.f, 0.f, 0.f);
    } else {
        // ---- V path: fp16 only
        float4 v = ((const float4*)V)[i];
        uint2 v16;
        {
            __half2 a = __floats2half2_rn(v.x, v.y);
            __half2 b = __floats2half2_rn(v.z, v.w);
            v16.x = *(uint32_t*)&a;
            v16.y = *(uint32_t*)&b;
        }
        ((uint2*)g_v16)[i] = v16;
        if (i < (BATCH * SEQ_Q) / 4) ((float4*)g_lacc)[i] = make_float4(0.f, 0.f, 0.f, 0.f);
    }
}

// ---------------- main attention kernel ----------------
static __device__ __forceinline__ void load_v_tile(uint32_t sb, int b, int kvrow,
                                                   int buf, int tid) {
    const char* g16 = (const char*)g_v16 + (size_t)(b * SEQ_V + kvrow) * HDIM * 2;
    uint32_t base = sb + SM_V + buf * VBUF_SZ;
#pragma unroll
    for (int i = 0; i < 8; i++) {
        uint32_t off = (uint32_t)(tid + i * NT) * 16;   // 1024 x 16B = 16KB
        CP16(base + SWZ(off), g16 + off);
    }
}

__global__ __launch_bounds__(NT, 2)
void attn_mma_kernel()
{
    extern __shared__ char smem[];
    const uint32_t sb = smem_u32(smem);
    const int tid = threadIdx.x;
    const int l = tid & 31, w = tid >> 5;
    const int qt = blockIdx.x & 255;     // (b, q64)
    const int kc = blockIdx.x >> 8;      // kv chunk 0..3
    const int b = qt >> 6;
    const int qrow0 = (qt & 63) * TQ;    // within batch
    const int kv0 = kc * KVCHUNK;

    // ---- prologue: Q (fp16 hi+lo) + V tile 0
    {
        const char* gqh = (const char*)g_qh + (size_t)(b * SEQ_Q + qrow0) * HDIM * 2;
        const char* gql = (const char*)g_ql + (size_t)(b * SEQ_Q + qrow0) * HDIM * 2;
#pragma unroll
        for (int i = 0; i < 4; i++) {
            uint32_t off = (uint32_t)(tid + i * NT) * 16;   // 512 x 16B = 8KB
            CP16(sb + SM_QH + SWZ(off), gqh + off);
            CP16(sb + SM_QL + SWZ(off), gql + off);
        }
        load_v_tile(sb, b, kv0, 0, tid);
        CP_COMMIT();
        CP_WAIT0();
        __syncthreads();
    }

    // ---- Q A-fragments (per warp: rows w*16..w*16+15)
    uint32_t aqh[4][4], aql[4][4];
    {
        int qrow = w * 16 + (l & 15);
#pragma unroll
        for (int kk = 0; kk < 4; kk++) {
            uint32_t off = SWZ((uint32_t)qrow * 128 + kk * 32 + ((l >> 4) & 1) * 16);
            LDSM4(aqh[kk], sb + SM_QH + off);
            LDSM4(aql[kk], sb + SM_QL + off);
        }
    }

    float oc[8][4];
#pragma unroll
    for (int f = 0; f < 8; f++) { oc[f][0] = oc[f][1] = oc[f][2] = oc[f][3] = 0.f; }
    float lsum0 = 0.f, lsum1 = 0.f;
    float m0 = -1e30f, m1 = -1e30f;      // per-row running max (log2 domain)

    for (int t = 0; t < TILES_PER_CTA; t++) {
        __syncthreads();
        if (t + 1 < TILES_PER_CTA) {
            load_v_tile(sb, b, kv0 + (t + 1) * TN, (t + 1) & 1, tid);
            CP_COMMIT();
            CP_WAIT1();
        } else {
            CP_WAIT0();
        }
        __syncthreads();

        const uint32_t v16b = sb + SM_V + (t & 1) * VBUF_SZ;

        // ---- S' = (Q*log2e) . V^T  (fp16x2: exact Q split, V fp16 once)
        float sc[16][4];
#pragma unroll
        for (int f = 0; f < 16; f++) { sc[f][0] = sc[f][1] = sc[f][2] = sc[f][3] = 0.f; }

#pragma unroll
        for (int kk = 0; kk < 4; kk++) {
#pragma unroll
            for (int np = 0; np < 8; np++) {
                uint32_t off = SWZ((uint32_t)(16 * np + (l & 7) + ((l >> 4) & 1) * 8) * 128
                                   + kk * 32 + ((l >> 3) & 1) * 16);
                uint32_t bh[4];
                LDSM4(bh, v16b + off);
                MMA_F16(sc[2 * np],     aqh[kk], bh[0], bh[1]);
                MMA_F16(sc[2 * np + 1], aqh[kk], bh[2], bh[3]);
                MMA_F16(sc[2 * np],     aql[kk], bh[0], bh[1]);
                MMA_F16(sc[2 * np + 1], aql[kk], bh[2], bh[3]);
            }
        }

        // ---- per-row running max over this tile (rows r and r+8)
        float tm0 = -1e30f, tm1 = -1e30f;
#pragma unroll
        for (int f = 0; f < 16; f++) {
            tm0 = fmaxf(tm0, fmaxf(sc[f][0], sc[f][1]));
            tm1 = fmaxf(tm1, fmaxf(sc[f][2], sc[f][3]));
        }
        tm0 = fmaxf(tm0, __shfl_xor_sync(0xFFFFFFFFu, tm0, 1));
        tm0 = fmaxf(tm0, __shfl_xor_sync(0xFFFFFFFFu, tm0, 2));
        tm1 = fmaxf(tm1, __shfl_xor_sync(0xFFFFFFFFu, tm1, 1));
        tm1 = fmaxf(tm1, __shfl_xor_sync(0xFFFFFFFFu, tm1, 2));
        float m0n = fmaxf(m0, tm0), m1n = fmaxf(m1, tm1);
        float rs0 = ex2f(m0 - m0n), rs1 = ex2f(m1 - m1n);   // 0 on first tile
        m0 = m0n; m1 = m1n;
        lsum0 *= rs0; lsum1 *= rs1;
#pragma unroll
        for (int f = 0; f < 8; f++) {
            oc[f][0] *= rs0; oc[f][1] *= rs0;
            oc[f][2] *= rs1; oc[f][3] *= rs1;
        }

        // ---- softmax: p = 2^(s'-m) in (0,1]
#pragma unroll
        for (int f = 0; f < 16; f++) {
            sc[f][0] = ex2f(sc[f][0] - m0);
            sc[f][1] = ex2f(sc[f][1] - m0);
            sc[f][2] = ex2f(sc[f][2] - m1);
            sc[f][3] = ex2f(sc[f][3] - m1);
        }

        // ---- O += P . V  single fp16 pass; denominator from the SAME
        //      fp16-rounded P so numerator/denominator weights are consistent
#pragma unroll
        for (int kcc = 0; kcc < 8; kcc++) {
            __half2 h0 = __floats2half2_rn(sc[2 * kcc][0],     sc[2 * kcc][1]);
            __half2 h1 = __floats2half2_rn(sc[2 * kcc][2],     sc[2 * kcc][3]);
            __half2 h2 = __floats2half2_rn(sc[2 * kcc + 1][0], sc[2 * kcc + 1][1]);
            __half2 h3 = __floats2half2_rn(sc[2 * kcc + 1][2], sc[2 * kcc + 1][3]);
            uint32_t ah[4];
            ah[0] = *(uint32_t*)&h0;
            ah[1] = *(uint32_t*)&h1;
            ah[2] = *(uint32_t*)&h2;
            ah[3] = *(uint32_t*)&h3;
            float2 f0 = __half22float2(h0), f1 = __half22float2(h1);
            float2 f2 = __half22float2(h2), f3 = __half22float2(h3);
            lsum0 += (f0.x + f0.y) + (f2.x + f2.y);
            lsum1 += (f1.x + f1.y) + (f3.x + f3.y);
#pragma unroll
            for (int dp = 0; dp < 4; dp++) {
                uint32_t off = SWZ((uint32_t)(16 * kcc + (l & 7) + ((l >> 3) & 1) * 8) * 128
                                   + dp * 32 + ((l >> 4) & 1) * 16);
                uint32_t vv[4];
                LDSM4T(vv, v16b + off);
                MMA_F16(oc[2 * dp],     ah, vv[0], vv[1]);
                MMA_F16(oc[2 * dp + 1], ah, vv[2], vv[3]);
            }
        }
    }

    // ---- merge partials at absolute scale: contribute O*2^m and l*2^m
    lsum0 += __shfl_xor_sync(0xFFFFFFFFu, lsum0, 1);
    lsum0 += __shfl_xor_sync(0xFFFFFFFFu, lsum0, 2);
    lsum1 += __shfl_xor_sync(0xFFFFFFFFu, lsum1, 1);
    lsum1 += __shfl_xor_sync(0xFFFFFFFFu, lsum1, 2);
    const float e0 = ex2f(m0);
    const float e1 = ex2f(m1);

    const int row0 = qrow0 + w * 16 + (l >> 2);
    float* oa = g_oacc + ((size_t)b * SEQ_Q + row0) * HDIM;
    float* ob = oa + 8 * HDIM;    // row0 + 8
    const int cb = 2 * (l & 3);
#pragma unroll
    for (int f = 0; f < 8; f++) {
        REDV2(oa + 8 * f + cb, oc[f][0] * e0, oc[f][1] * e0);
        REDV2(ob + 8 * f + cb, oc[f][2] * e1, oc[f][3] * e1);
    }
    if ((l & 3) == 0) {
        atomicAdd(g_lacc + (size_t)b * SEQ_Q + row0,     lsum0 * e0);
        atomicAdd(g_lacc + (size_t)b * SEQ_Q + row0 + 8, lsum1 * e1);
    }
}

// ---------------- normalize: O = acc / l ----------------
__global__ void normalize_kernel(float* __restrict__ O) {
    int i = blockIdx.x * blockDim.x + threadIdx.x;   // float4 units, 262144
    int row = i >> 4;                                // 16 float4 per row
    float inv = 1.0f / g_lacc[row];
    float4 v = ((const float4*)g_oacc)[i];
    ((float4*)O)[i] = make_float4(v.x * inv, v.y * inv, v.z * inv, v.w * inv);
}

extern "C" void kernel_launch(void* const* d_in, const int* in_sizes, int n_in,
                              void* d_out, int out_size)
{
    const float* Q = (const float*)d_in[0];
    const float* V = (const float*)d_in[1];
    float* O = (float*)d_out;

    convert_kernel<<<2048, 256>>>(Q, V);

    cudaFuncSetAttribute(attn_mma_kernel,
                         cudaFuncAttributeMaxDynamicSharedMemorySize, SMEM_TOTAL);
    attn_mma_kernel<<<256 * KVSPLIT, NT, SMEM_TOTAL>>>();

    normalize_kernel<<<(BATCH * SEQ_Q * HDIM / 4) / 256, 256>>>(O);
}